// round 1
// baseline (speedup 1.0000x reference)
#include <cuda_runtime.h>

#define N_VAR  100000
#define N_CSTR 50000
#define NEDGE  1000000
#define D      64
#define BN_EPS 1e-5f

typedef unsigned long long u64;

// ---------------- scratch (static __device__ — no allocs allowed) ----------------
__device__ float g_xn_node[N_VAR * D];    // BN'd var feats
__device__ float g_xn_cstr[N_CSTR * D];   // BN'd cstr feats
__device__ float g_agg_node[N_VAR * D];   // mean-aggregated messages (node side)
__device__ float g_agg_cstr[N_CSTR * D];
__device__ int2  g_e_node[NEDGE];         // CSR-by-dst: (src, attr_bits)
__device__ int2  g_e_cstr[NEDGE];         // CSR-by-src: (dst, attr_bits)
__device__ int   g_deg_node[N_VAR];
__device__ int   g_deg_cstr[N_CSTR];
__device__ int   g_row_node[N_VAR];
__device__ int   g_row_cstr[N_CSTR];
__device__ int   g_cur_node[N_VAR];
__device__ int   g_cur_cstr[N_CSTR];
__device__ float g_stats_node[2 * D];     // [sum(64) | sumsq(64)]
__device__ float g_stats_cstr[2 * D];
__device__ float g_scale_node[D], g_shift_node[D];
__device__ float g_scale_cstr[D], g_shift_cstr[D];
__device__ int   g_bsum_node[32];
__device__ int   g_bsum_cstr[32];

// ---------------- small helpers ----------------
__device__ __forceinline__ u64 fma2(u64 a, u64 b, u64 c) {
    u64 d;
    asm("fma.rn.f32x2 %0, %1, %2, %3;" : "=l"(d) : "l"(a), "l"(b), "l"(c));
    return d;
}
__device__ __forceinline__ float2 unpk(u64 v) {
    float2 f;
    asm("mov.b64 {%0,%1}, %2;" : "=f"(f.x), "=f"(f.y) : "l"(v));
    return f;
}

// ---------------- 0: zero scratch ----------------
__global__ void k_zero() {
    int i = blockIdx.x * blockDim.x + threadIdx.x;
    int stride = gridDim.x * blockDim.x;
    for (int j = i; j < N_VAR; j += stride) g_deg_node[j] = 0;
    for (int j = i; j < N_CSTR; j += stride) g_deg_cstr[j] = 0;
    if (i < 2 * D) { g_stats_node[i] = 0.f; g_stats_cstr[i] = 0.f; }
}

// ---------------- 1: BN column stats (sum, sumsq) ----------------
__global__ void k_bnstats(const float* __restrict__ x, int n, int which) {
    float* stats = which ? g_stats_cstr : g_stats_node;
    int c = threadIdx.x;                     // column 0..63
    int step = gridDim.x * blockDim.y;
    float s = 0.f, q = 0.f;
    for (int r = blockIdx.x * blockDim.y + threadIdx.y; r < n; r += step) {
        float v = x[(size_t)r * D + c];
        s += v; q = fmaf(v, v, q);
    }
    __shared__ float shs[4][64], shq[4][64];
    shs[threadIdx.y][c] = s; shq[threadIdx.y][c] = q;
    __syncthreads();
    if (threadIdx.y == 0) {
        float S = shs[0][c] + shs[1][c] + shs[2][c] + shs[3][c];
        float Q = shq[0][c] + shq[1][c] + shq[2][c] + shq[3][c];
        atomicAdd(&stats[c], S);
        atomicAdd(&stats[D + c], Q);
    }
}

// ---------------- 2: finalize BN scale/shift ----------------
__global__ void k_finstats(const float* __restrict__ gn, const float* __restrict__ bn,
                           const float* __restrict__ gc, const float* __restrict__ bc) {
    int c = threadIdx.x;
    if (c < D) {
        float m = g_stats_node[c] / (float)N_VAR;
        float v = g_stats_node[D + c] / (float)N_VAR - m * m;
        float sc = gn[c] * rsqrtf(v + BN_EPS);
        g_scale_node[c] = sc;
        g_shift_node[c] = fmaf(-m, sc, bn[c]);
    } else if (c < 2 * D) {
        int cc = c - D;
        float m = g_stats_cstr[cc] / (float)N_CSTR;
        float v = g_stats_cstr[D + cc] / (float)N_CSTR - m * m;
        float sc = gc[cc] * rsqrtf(v + BN_EPS);
        g_scale_cstr[cc] = sc;
        g_shift_cstr[cc] = fmaf(-m, sc, bc[cc]);
    }
}

// ---------------- 3: normalize (x*scale + shift) ----------------
__global__ void k_norm(const float* __restrict__ x, int n, int which) {
    float* y = which ? g_xn_cstr : g_xn_node;
    const float* sc = which ? g_scale_cstr : g_scale_node;
    const float* sf = which ? g_shift_cstr : g_shift_node;
    __shared__ float ssc[64], ssh[64];
    if (threadIdx.x < 64) { ssc[threadIdx.x] = sc[threadIdx.x]; ssh[threadIdx.x] = sf[threadIdx.x]; }
    __syncthreads();
    int total = n * (D / 4);
    const float4* xin = (const float4*)x;
    float4* yo = (float4*)y;
    for (int i = blockIdx.x * blockDim.x + threadIdx.x; i < total; i += gridDim.x * blockDim.x) {
        int c = (i & 15) * 4;
        float4 v = xin[i];
        v.x = fmaf(v.x, ssc[c + 0], ssh[c + 0]);
        v.y = fmaf(v.y, ssc[c + 1], ssh[c + 1]);
        v.z = fmaf(v.z, ssc[c + 2], ssh[c + 2]);
        v.w = fmaf(v.w, ssc[c + 3], ssh[c + 3]);
        yo[i] = v;
    }
}

// ---------------- 4: degree histogram ----------------
__global__ void k_hist(const int* __restrict__ src, const int* __restrict__ dst) {
    for (int e = blockIdx.x * blockDim.x + threadIdx.x; e < NEDGE; e += gridDim.x * blockDim.x) {
        atomicAdd(&g_deg_node[dst[e]], 1);
        atomicAdd(&g_deg_cstr[src[e]], 1);
    }
}

// ---------------- 5: exclusive scan (3 kernels) ----------------
#define SCAN_T 256
#define SCAN_I 16
#define SCAN_CHUNK (SCAN_T * SCAN_I)
#define NB_NODE ((N_VAR + SCAN_CHUNK - 1) / SCAN_CHUNK)   // 25
#define NB_CSTR ((N_CSTR + SCAN_CHUNK - 1) / SCAN_CHUNK)  // 13

__global__ void k_scan1(int which) {
    const int* in = which ? g_deg_cstr : g_deg_node;
    int* out = which ? g_row_cstr : g_row_node;
    int* bsum = which ? g_bsum_cstr : g_bsum_node;
    int n = which ? N_CSTR : N_VAR;
    __shared__ int sh[SCAN_T];
    int t = threadIdx.x;
    int base = blockIdx.x * SCAN_CHUNK + t * SCAN_I;
    int loc[SCAN_I];
    int s = 0;
#pragma unroll
    for (int i = 0; i < SCAN_I; i++) {
        int idx = base + i;
        int v = (idx < n) ? in[idx] : 0;
        loc[i] = s; s += v;
    }
    sh[t] = s;
    __syncthreads();
    for (int off = 1; off < SCAN_T; off <<= 1) {
        int v = (t >= off) ? sh[t - off] : 0;
        __syncthreads();
        sh[t] += v;
        __syncthreads();
    }
    int pre = (t > 0) ? sh[t - 1] : 0;
#pragma unroll
    for (int i = 0; i < SCAN_I; i++) {
        int idx = base + i;
        if (idx < n) out[idx] = pre + loc[i];
    }
    if (t == SCAN_T - 1) bsum[blockIdx.x] = sh[t];
}

__global__ void k_scan2() {
    int t = threadIdx.x;
    if (t == 0) {
        int s = 0;
        for (int i = 0; i < NB_NODE; i++) { int v = g_bsum_node[i]; g_bsum_node[i] = s; s += v; }
    }
    if (t == 1) {
        int s = 0;
        for (int i = 0; i < NB_CSTR; i++) { int v = g_bsum_cstr[i]; g_bsum_cstr[i] = s; s += v; }
    }
}

__global__ void k_scan3(int which) {
    int* row = which ? g_row_cstr : g_row_node;
    int* cur = which ? g_cur_cstr : g_cur_node;
    const int* bsum = which ? g_bsum_cstr : g_bsum_node;
    int n = which ? N_CSTR : N_VAR;
    int add = bsum[blockIdx.x];
    int base = blockIdx.x * SCAN_CHUNK;
    for (int i = threadIdx.x; i < SCAN_CHUNK; i += SCAN_T) {
        int idx = base + i;
        if (idx < n) { int v = row[idx] + add; row[idx] = v; cur[idx] = v; }
    }
}

// ---------------- 6: scatter edges into CSR slots ----------------
__global__ void k_scatter(const int* __restrict__ src, const int* __restrict__ dst,
                          const float* __restrict__ attr) {
    for (int e = blockIdx.x * blockDim.x + threadIdx.x; e < NEDGE; e += gridDim.x * blockDim.x) {
        int s = src[e], d = dst[e];
        int a = __float_as_int(attr[e]);
        int p = atomicAdd(&g_cur_node[d], 1);
        g_e_node[p] = make_int2(s, a);
        int q = atomicAdd(&g_cur_cstr[s], 1);
        g_e_cstr[q] = make_int2(d, a);
    }
}

// ---------------- 7: warp-per-node mean aggregation (atomic-free) ----------------
__global__ void k_gather(int which) {
    const int2* __restrict__ eb = which ? g_e_cstr : g_e_node;
    const int* __restrict__ row = which ? g_row_cstr : g_row_node;
    const int* __restrict__ deg = which ? g_deg_cstr : g_deg_node;
    const float* __restrict__ xs = which ? g_xn_node : g_xn_cstr;  // node-side gathers cstr feats, cstr-side gathers node feats
    float* __restrict__ agg = which ? g_agg_cstr : g_agg_node;
    int n = which ? N_CSTR : N_VAR;

    int w = (blockIdx.x * blockDim.x + threadIdx.x) >> 5;
    if (w >= n) return;
    int lane = threadIdx.x & 31;
    int beg = __ldg(&row[w]);
    int d = __ldg(&deg[w]);
    const float2* xs2 = (const float2*)xs;
    float2 acc = make_float2(0.f, 0.f);
    int i = 0;
    for (; i + 2 <= d; i += 2) {
        int2 e0 = __ldg(&eb[beg + i]);
        int2 e1 = __ldg(&eb[beg + i + 1]);
        float a0 = __int_as_float(e0.y), a1 = __int_as_float(e1.y);
        float2 x0 = xs2[(size_t)e0.x * 32 + lane];
        float2 x1 = xs2[(size_t)e1.x * 32 + lane];
        acc.x = fmaf(x0.x, a0, acc.x); acc.y = fmaf(x0.y, a0, acc.y);
        acc.x = fmaf(x1.x, a1, acc.x); acc.y = fmaf(x1.y, a1, acc.y);
    }
    if (i < d) {
        int2 e0 = __ldg(&eb[beg + i]);
        float a0 = __int_as_float(e0.y);
        float2 x0 = xs2[(size_t)e0.x * 32 + lane];
        acc.x = fmaf(x0.x, a0, acc.x); acc.y = fmaf(x0.y, a0, acc.y);
    }
    float inv = 1.f / fmaxf((float)d, 1.f);
    ((float2*)agg)[(size_t)w * 32 + lane] = make_float2(acc.x * inv, acc.y * inv);
}

// ---------------- 8: dual 64x64 matvec + bias + residual + relu ----------------
// out = relu( agg @ Wrel^T + b + xn @ (Wroot^T + I) )   (residual folded into Wroot diag)
__global__ void __launch_bounds__(128) k_out(const float* __restrict__ Wrel,
                                             const float* __restrict__ brel,
                                             const float* __restrict__ Wroot,
                                             float* __restrict__ out, int which) {
    const float* agg = which ? g_agg_cstr : g_agg_node;
    const float* xn  = which ? g_xn_cstr : g_xn_node;
    int n = which ? N_CSTR : N_VAR;

    __shared__ float sWrel[D * D];
    __shared__ float sWroot[D * D];
    __shared__ float sOut[4][32][17];
    __shared__ float sb[D];

    for (int i = threadIdx.x; i < D * D; i += blockDim.x) {
        sWrel[i] = Wrel[i];
        int j = i >> 6, k = i & 63;
        sWroot[i] = Wroot[i] + ((j == k) ? 1.f : 0.f);
    }
    if (threadIdx.x < D) sb[threadIdx.x] = brel[threadIdx.x];
    __syncthreads();

    int v = blockIdx.x * 128 + threadIdx.x;
    int vl = min(v, n - 1);

    // load agg + xn rows packed as f32x2 pairs (registers)
    u64 ap[32], xp[32];
    const ulonglong2* pa = (const ulonglong2*)(agg + (size_t)vl * D);
    const ulonglong2* px = (const ulonglong2*)(xn + (size_t)vl * D);
#pragma unroll
    for (int i = 0; i < 16; i++) {
        ulonglong2 t = pa[i]; ap[2 * i] = t.x; ap[2 * i + 1] = t.y;
        t = px[i];            xp[2 * i] = t.x; xp[2 * i + 1] = t.y;
    }

    int w = threadIdx.x >> 5, lane = threadIdx.x & 31;
    int v0w = blockIdx.x * 128 + w * 32;

    for (int jt = 0; jt < D; jt += 16) {
        for (int jj = 0; jj < 16; jj++) {
            int j = jt + jj;
            const ulonglong2* wr = (const ulonglong2*)(sWrel + j * D);
            const ulonglong2* wo = (const ulonglong2*)(sWroot + j * D);
            u64 a0 = 0, a1 = 0, b0 = 0, b1 = 0;
#pragma unroll
            for (int kk = 0; kk < 16; kk++) {
                ulonglong2 w1 = wr[kk];   // broadcast LDS.128
                ulonglong2 w2 = wo[kk];
                a0 = fma2(ap[2 * kk],     w1.x, a0);
                a1 = fma2(ap[2 * kk + 1], w1.y, a1);
                b0 = fma2(xp[2 * kk],     w2.x, b0);
                b1 = fma2(xp[2 * kk + 1], w2.y, b1);
            }
            float2 fa0 = unpk(a0), fa1 = unpk(a1), fb0 = unpk(b0), fb1 = unpk(b1);
            float r = ((fa0.x + fa0.y) + (fa1.x + fa1.y)) +
                      ((fb0.x + fb0.y) + (fb1.x + fb1.y)) + sb[j];
            sOut[w][lane][jj] = fmaxf(r, 0.f);
        }
        __syncwarp();
        // coalesced flush: 2 rows x 16 cols per iteration
        int col = lane & 15, rh = lane >> 4;
        for (int r2 = 0; r2 < 32; r2 += 2) {
            int rrow = r2 + rh;
            int node = v0w + rrow;
            if (node < n) out[(size_t)node * D + jt + col] = sOut[w][rrow][col];
        }
        __syncwarp();
    }
}

// ---------------- launch ----------------
extern "C" void kernel_launch(void* const* d_in, const int* in_sizes, int n_in,
                              void* d_out, int out_size) {
    (void)in_sizes; (void)n_in; (void)out_size;
    const float* var_feats   = (const float*)d_in[0];
    const float* cstr_feats  = (const float*)d_in[1];
    const int*   edge_src    = (const int*)d_in[2];
    const int*   edge_dst    = (const int*)d_in[3];
    const float* edge_attr   = (const float*)d_in[4];
    const float* gn          = (const float*)d_in[5];
    const float* bn          = (const float*)d_in[6];
    const float* gc          = (const float*)d_in[7];
    const float* bc          = (const float*)d_in[8];
    const float* node_rel_w  = (const float*)d_in[9];
    const float* node_rel_b  = (const float*)d_in[10];
    const float* node_root_w = (const float*)d_in[11];
    const float* cstr_rel_w  = (const float*)d_in[12];
    const float* cstr_rel_b  = (const float*)d_in[13];
    const float* cstr_root_w = (const float*)d_in[14];

    float* out_node = (float*)d_out;
    float* out_cstr = out_node + (size_t)N_VAR * D;

    k_zero<<<256, 256>>>();
    k_bnstats<<<240, dim3(64, 4)>>>(var_feats, N_VAR, 0);
    k_bnstats<<<240, dim3(64, 4)>>>(cstr_feats, N_CSTR, 1);
    k_finstats<<<1, 128>>>(gn, bn, gc, bc);
    k_norm<<<800, 256>>>(var_feats, N_VAR, 0);
    k_norm<<<400, 256>>>(cstr_feats, N_CSTR, 1);
    k_hist<<<2048, 256>>>(edge_src, edge_dst);
    k_scan1<<<NB_NODE, SCAN_T>>>(0);
    k_scan1<<<NB_CSTR, SCAN_T>>>(1);
    k_scan2<<<1, 2>>>();
    k_scan3<<<NB_NODE, SCAN_T>>>(0);
    k_scan3<<<NB_CSTR, SCAN_T>>>(1);
    k_scatter<<<2048, 256>>>(edge_src, edge_dst, edge_attr);
    k_gather<<<(N_VAR * 32 + 255) / 256, 256>>>(0);
    k_gather<<<(N_CSTR * 32 + 255) / 256, 256>>>(1);
    k_out<<<(N_VAR + 127) / 128, 128>>>(node_rel_w, node_rel_b, node_root_w, out_node, 0);
    k_out<<<(N_CSTR + 127) / 128, 128>>>(cstr_rel_w, cstr_rel_b, cstr_root_w, out_cstr, 1);
}

// round 3
// speedup vs baseline: 1.0064x; 1.0064x over previous
#include <cuda_runtime.h>
#include <cuda_bf16.h>

#define N_VAR  100000
#define N_CSTR 50000
#define NEDGE  1000000
#define D      64
#define BN_EPS 1e-5f

typedef unsigned long long u64;

// ---------------- scratch (static __device__ — no allocs allowed) ----------------
__device__ __nv_bfloat162 g_bf_node[N_VAR * 32];   // raw var feats, bf16
__device__ __nv_bfloat162 g_bf_cstr[N_CSTR * 32];  // raw cstr feats, bf16
__device__ float g_agg_node[N_VAR * D];            // mean-aggregated messages (normalized space)
__device__ float g_agg_cstr[N_CSTR * D];
__device__ int2  g_e_node[NEDGE];                  // CSR-by-dst: (src, attr_bits)
__device__ int2  g_e_cstr[NEDGE];                  // CSR-by-src: (dst, attr_bits)
__device__ int   g_deg_node[N_VAR];
__device__ int   g_deg_cstr[N_CSTR];
__device__ int   g_row_node[N_VAR];
__device__ int   g_row_cstr[N_CSTR];
__device__ int   g_cur_node[N_VAR];
__device__ int   g_cur_cstr[N_CSTR];
__device__ float g_stats_node[2 * D];              // [sum(64) | sumsq(64)]
__device__ float g_stats_cstr[2 * D];
__device__ float g_scale_node[D], g_shift_node[D];
__device__ float g_scale_cstr[D], g_shift_cstr[D];
__device__ int   g_bsum_node[32];
__device__ int   g_bsum_cstr[32];

// ---------------- small helpers ----------------
__device__ __forceinline__ u64 fma2(u64 a, u64 b, u64 c) {
    u64 d;
    asm("fma.rn.f32x2 %0, %1, %2, %3;" : "=l"(d) : "l"(a), "l"(b), "l"(c));
    return d;
}
__device__ __forceinline__ float2 unpk(u64 v) {
    float2 f;
    asm("mov.b64 {%0,%1}, %2;" : "=f"(f.x), "=f"(f.y) : "l"(v));
    return f;
}

// ---------------- 0: zero scratch ----------------
__global__ void k_zero() {
    int i = blockIdx.x * blockDim.x + threadIdx.x;
    int stride = gridDim.x * blockDim.x;
    for (int j = i; j < N_VAR; j += stride) g_deg_node[j] = 0;
    for (int j = i; j < N_CSTR; j += stride) g_deg_cstr[j] = 0;
    if (i < 2 * D) { g_stats_node[i] = 0.f; g_stats_cstr[i] = 0.f; }
}

// ---------------- 1: BN column stats (sum, sumsq) + fused bf16 conversion ----------------
__global__ void k_bnstats(const float* __restrict__ x, int n, int which) {
    float* stats = which ? g_stats_cstr : g_stats_node;
    __nv_bfloat16* bf = (__nv_bfloat16*)(which ? g_bf_cstr : g_bf_node);
    int c = threadIdx.x;                     // column 0..63
    int step = gridDim.x * blockDim.y;
    float s = 0.f, q = 0.f;
    for (int r = blockIdx.x * blockDim.y + threadIdx.y; r < n; r += step) {
        float v = x[(size_t)r * D + c];
        bf[(size_t)r * D + c] = __float2bfloat16_rn(v);
        s += v; q = fmaf(v, v, q);
    }
    __shared__ float shs[4][64], shq[4][64];
    shs[threadIdx.y][c] = s; shq[threadIdx.y][c] = q;
    __syncthreads();
    if (threadIdx.y == 0) {
        float S = shs[0][c] + shs[1][c] + shs[2][c] + shs[3][c];
        float Q = shq[0][c] + shq[1][c] + shq[2][c] + shq[3][c];
        atomicAdd(&stats[c], S);
        atomicAdd(&stats[D + c], Q);
    }
}

// ---------------- 2: finalize BN scale/shift ----------------
__global__ void k_finstats(const float* __restrict__ gn, const float* __restrict__ bn,
                           const float* __restrict__ gc, const float* __restrict__ bc) {
    int c = threadIdx.x;
    if (c < D) {
        float m = g_stats_node[c] / (float)N_VAR;
        float v = g_stats_node[D + c] / (float)N_VAR - m * m;
        float sc = gn[c] * rsqrtf(v + BN_EPS);
        g_scale_node[c] = sc;
        g_shift_node[c] = fmaf(-m, sc, bn[c]);
    } else if (c < 2 * D) {
        int cc = c - D;
        float m = g_stats_cstr[cc] / (float)N_CSTR;
        float v = g_stats_cstr[D + cc] / (float)N_CSTR - m * m;
        float sc = gc[cc] * rsqrtf(v + BN_EPS);
        g_scale_cstr[cc] = sc;
        g_shift_cstr[cc] = fmaf(-m, sc, bc[cc]);
    }
}

// ---------------- 3: degree histogram ----------------
__global__ void k_hist(const int* __restrict__ src, const int* __restrict__ dst) {
    for (int e = blockIdx.x * blockDim.x + threadIdx.x; e < NEDGE; e += gridDim.x * blockDim.x) {
        atomicAdd(&g_deg_node[dst[e]], 1);
        atomicAdd(&g_deg_cstr[src[e]], 1);
    }
}

// ---------------- 4: exclusive scan (3 kernels) ----------------
#define SCAN_T 256
#define SCAN_I 16
#define SCAN_CHUNK (SCAN_T * SCAN_I)
#define NB_NODE ((N_VAR + SCAN_CHUNK - 1) / SCAN_CHUNK)   // 25
#define NB_CSTR ((N_CSTR + SCAN_CHUNK - 1) / SCAN_CHUNK)  // 13

__global__ void k_scan1(int which) {
    const int* in = which ? g_deg_cstr : g_deg_node;
    int* out = which ? g_row_cstr : g_row_node;
    int* bsum = which ? g_bsum_cstr : g_bsum_node;
    int n = which ? N_CSTR : N_VAR;
    __shared__ int sh[SCAN_T];
    int t = threadIdx.x;
    int base = blockIdx.x * SCAN_CHUNK + t * SCAN_I;
    int loc[SCAN_I];
    int s = 0;
#pragma unroll
    for (int i = 0; i < SCAN_I; i++) {
        int idx = base + i;
        int v = (idx < n) ? in[idx] : 0;
        loc[i] = s; s += v;
    }
    sh[t] = s;
    __syncthreads();
    for (int off = 1; off < SCAN_T; off <<= 1) {
        int v = (t >= off) ? sh[t - off] : 0;
        __syncthreads();
        sh[t] += v;
        __syncthreads();
    }
    int pre = (t > 0) ? sh[t - 1] : 0;
#pragma unroll
    for (int i = 0; i < SCAN_I; i++) {
        int idx = base + i;
        if (idx < n) out[idx] = pre + loc[i];
    }
    if (t == SCAN_T - 1) bsum[blockIdx.x] = sh[t];
}

__global__ void k_scan2() {
    int t = threadIdx.x;
    if (t == 0) {
        int s = 0;
        for (int i = 0; i < NB_NODE; i++) { int v = g_bsum_node[i]; g_bsum_node[i] = s; s += v; }
    }
    if (t == 1) {
        int s = 0;
        for (int i = 0; i < NB_CSTR; i++) { int v = g_bsum_cstr[i]; g_bsum_cstr[i] = s; s += v; }
    }
}

__global__ void k_scan3(int which) {
    int* row = which ? g_row_cstr : g_row_node;
    int* cur = which ? g_cur_cstr : g_cur_node;
    const int* bsum = which ? g_bsum_cstr : g_bsum_node;
    int n = which ? N_CSTR : N_VAR;
    int add = bsum[blockIdx.x];
    int base = blockIdx.x * SCAN_CHUNK;
    for (int i = threadIdx.x; i < SCAN_CHUNK; i += SCAN_T) {
        int idx = base + i;
        if (idx < n) { int v = row[idx] + add; row[idx] = v; cur[idx] = v; }
    }
}

// ---------------- 5: scatter edges into CSR slots ----------------
__global__ void k_scatter(const int* __restrict__ src, const int* __restrict__ dst,
                          const float* __restrict__ attr) {
    for (int e = blockIdx.x * blockDim.x + threadIdx.x; e < NEDGE; e += gridDim.x * blockDim.x) {
        int s = src[e], d = dst[e];
        int a = __float_as_int(attr[e]);
        int p = atomicAdd(&g_cur_node[d], 1);
        g_e_node[p] = make_int2(s, a);
        int q = atomicAdd(&g_cur_cstr[s], 1);
        g_e_cstr[q] = make_int2(d, a);
    }
}

// ---------------- 6: warp-per-node mean aggregation (bf16 rows, affine folded) ----------------
// agg_c = scale_c * (sum_e x_raw_c * ew) / max(d,1) + shift_c * (sum_e ew) / max(d,1)
__global__ void k_gather(int which) {
    const int2* __restrict__ eb = which ? g_e_cstr : g_e_node;
    const int* __restrict__ row = which ? g_row_cstr : g_row_node;
    const int* __restrict__ deg = which ? g_deg_cstr : g_deg_node;
    const __nv_bfloat162* __restrict__ xs = which ? g_bf_node : g_bf_cstr;  // source side features
    const float* __restrict__ sc = which ? g_scale_node : g_scale_cstr;     // affine of SOURCE side
    const float* __restrict__ sf = which ? g_shift_node : g_shift_cstr;
    float* __restrict__ agg = which ? g_agg_cstr : g_agg_node;
    int n = which ? N_CSTR : N_VAR;

    int w = (blockIdx.x * blockDim.x + threadIdx.x) >> 5;
    if (w >= n) return;
    int lane = threadIdx.x & 31;
    int beg = __ldg(&row[w]);
    int d = __ldg(&deg[w]);
    float2 acc = make_float2(0.f, 0.f);
    float sew = 0.f;
    int i = 0;
    for (; i + 4 <= d; i += 4) {
        int2 e0 = __ldg(&eb[beg + i]);
        int2 e1 = __ldg(&eb[beg + i + 1]);
        int2 e2 = __ldg(&eb[beg + i + 2]);
        int2 e3 = __ldg(&eb[beg + i + 3]);
        float a0 = __int_as_float(e0.y), a1 = __int_as_float(e1.y);
        float a2 = __int_as_float(e2.y), a3 = __int_as_float(e3.y);
        float2 x0 = __bfloat1622float2(xs[(size_t)e0.x * 32 + lane]);
        float2 x1 = __bfloat1622float2(xs[(size_t)e1.x * 32 + lane]);
        float2 x2 = __bfloat1622float2(xs[(size_t)e2.x * 32 + lane]);
        float2 x3 = __bfloat1622float2(xs[(size_t)e3.x * 32 + lane]);
        acc.x = fmaf(x0.x, a0, acc.x); acc.y = fmaf(x0.y, a0, acc.y);
        acc.x = fmaf(x1.x, a1, acc.x); acc.y = fmaf(x1.y, a1, acc.y);
        acc.x = fmaf(x2.x, a2, acc.x); acc.y = fmaf(x2.y, a2, acc.y);
        acc.x = fmaf(x3.x, a3, acc.x); acc.y = fmaf(x3.y, a3, acc.y);
        sew += (a0 + a1) + (a2 + a3);
    }
    for (; i < d; i++) {
        int2 e0 = __ldg(&eb[beg + i]);
        float a0 = __int_as_float(e0.y);
        float2 x0 = __bfloat1622float2(xs[(size_t)e0.x * 32 + lane]);
        acc.x = fmaf(x0.x, a0, acc.x); acc.y = fmaf(x0.y, a0, acc.y);
        sew += a0;
    }
    float inv = 1.f / fmaxf((float)d, 1.f);
    float2 scl = ((const float2*)sc)[lane];
    float2 shf = ((const float2*)sf)[lane];
    float2 r;
    r.x = (scl.x * acc.x + shf.x * sew) * inv;
    r.y = (scl.y * acc.y + shf.y * sew) * inv;
    ((float2*)agg)[(size_t)w * 32 + lane] = r;
}

// ---------------- 7: dual 64x64 matvec + bias + residual + relu (affine on the fly) ----------------
// out = relu( agg @ Wrel^T + b + (scale*x_raw+shift) @ (Wroot^T + I) )
__global__ void __launch_bounds__(128) k_out(const float* __restrict__ Wrel,
                                             const float* __restrict__ brel,
                                             const float* __restrict__ Wroot,
                                             const float* __restrict__ xraw,
                                             float* __restrict__ out, int which) {
    const float* agg = which ? g_agg_cstr : g_agg_node;
    const float* sc = which ? g_scale_cstr : g_scale_node;   // affine of DST side
    const float* sf = which ? g_shift_cstr : g_shift_node;
    int n = which ? N_CSTR : N_VAR;

    __shared__ float sWrel[D * D];
    __shared__ float sWroot[D * D];
    __shared__ float sOut[4][32][17];
    __shared__ float sb[D];
    __shared__ u64 ssc[32], ssh[32];

    for (int i = threadIdx.x; i < D * D; i += blockDim.x) {
        sWrel[i] = Wrel[i];
        int j = i >> 6, k = i & 63;
        sWroot[i] = Wroot[i] + ((j == k) ? 1.f : 0.f);
    }
    if (threadIdx.x < D) sb[threadIdx.x] = brel[threadIdx.x];
    if (threadIdx.x < 32) {
        ssc[threadIdx.x] = ((const u64*)sc)[threadIdx.x];
        ssh[threadIdx.x] = ((const u64*)sf)[threadIdx.x];
    }
    __syncthreads();

    int v = blockIdx.x * 128 + threadIdx.x;
    int vl = min(v, n - 1);

    // load agg + raw rows packed as f32x2 pairs; apply affine to raw
    u64 ap[32], xp[32];
    const ulonglong2* pa = (const ulonglong2*)(agg + (size_t)vl * D);
    const ulonglong2* px = (const ulonglong2*)(xraw + (size_t)vl * D);
#pragma unroll
    for (int i = 0; i < 16; i++) {
        ulonglong2 t = pa[i]; ap[2 * i] = t.x; ap[2 * i + 1] = t.y;
        t = px[i];
        xp[2 * i]     = fma2(t.x, ssc[2 * i],     ssh[2 * i]);
        xp[2 * i + 1] = fma2(t.y, ssc[2 * i + 1], ssh[2 * i + 1]);
    }

    int w = threadIdx.x >> 5, lane = threadIdx.x & 31;
    int v0w = blockIdx.x * 128 + w * 32;

    for (int jt = 0; jt < D; jt += 16) {
        for (int jj = 0; jj < 16; jj++) {
            int j = jt + jj;
            const ulonglong2* wr = (const ulonglong2*)(sWrel + j * D);
            const ulonglong2* wo = (const ulonglong2*)(sWroot + j * D);
            u64 a0 = 0, a1 = 0, b0 = 0, b1 = 0;
#pragma unroll
            for (int kk = 0; kk < 16; kk++) {
                ulonglong2 w1 = wr[kk];   // broadcast LDS.128
                ulonglong2 w2 = wo[kk];
                a0 = fma2(ap[2 * kk],     w1.x, a0);
                a1 = fma2(ap[2 * kk + 1], w1.y, a1);
                b0 = fma2(xp[2 * kk],     w2.x, b0);
                b1 = fma2(xp[2 * kk + 1], w2.y, b1);
            }
            float2 fa0 = unpk(a0), fa1 = unpk(a1), fb0 = unpk(b0), fb1 = unpk(b1);
            float r = ((fa0.x + fa0.y) + (fa1.x + fa1.y)) +
                      ((fb0.x + fb0.y) + (fb1.x + fb1.y)) + sb[j];
            sOut[w][lane][jj] = fmaxf(r, 0.f);
        }
        __syncwarp();
        // coalesced flush: 2 rows x 16 cols per iteration
        int col = lane & 15, rh = lane >> 4;
        for (int r2 = 0; r2 < 32; r2 += 2) {
            int rrow = r2 + rh;
            int node = v0w + rrow;
            if (node < n) out[(size_t)node * D + jt + col] = sOut[w][rrow][col];
        }
        __syncwarp();
    }
}

// ---------------- launch ----------------
extern "C" void kernel_launch(void* const* d_in, const int* in_sizes, int n_in,
                              void* d_out, int out_size) {
    (void)in_sizes; (void)n_in; (void)out_size;
    const float* var_feats   = (const float*)d_in[0];
    const float* cstr_feats  = (const float*)d_in[1];
    const int*   edge_src    = (const int*)d_in[2];
    const int*   edge_dst    = (const int*)d_in[3];
    const float* edge_attr   = (const float*)d_in[4];
    const float* gn          = (const float*)d_in[5];
    const float* bn          = (const float*)d_in[6];
    const float* gc          = (const float*)d_in[7];
    const float* bc          = (const float*)d_in[8];
    const float* node_rel_w  = (const float*)d_in[9];
    const float* node_rel_b  = (const float*)d_in[10];
    const float* node_root_w = (const float*)d_in[11];
    const float* cstr_rel_w  = (const float*)d_in[12];
    const float* cstr_rel_b  = (const float*)d_in[13];
    const float* cstr_root_w = (const float*)d_in[14];

    float* out_node = (float*)d_out;
    float* out_cstr = out_node + (size_t)N_VAR * D;

    k_zero<<<391, 256>>>();
    k_bnstats<<<296, dim3(64, 4)>>>(var_feats, N_VAR, 0);
    k_bnstats<<<296, dim3(64, 4)>>>(cstr_feats, N_CSTR, 1);
    k_finstats<<<1, 128>>>(gn, bn, gc, bc);
    k_hist<<<2048, 256>>>(edge_src, edge_dst);
    k_scan1<<<NB_NODE, SCAN_T>>>(0);
    k_scan1<<<NB_CSTR, SCAN_T>>>(1);
    k_scan2<<<1, 2>>>();
    k_scan3<<<NB_NODE, SCAN_T>>>(0);
    k_scan3<<<NB_CSTR, SCAN_T>>>(1);
    k_scatter<<<2048, 256>>>(edge_src, edge_dst, edge_attr);
    k_gather<<<(N_VAR * 32 + 255) / 256, 256>>>(0);
    k_gather<<<(N_CSTR * 32 + 255) / 256, 256>>>(1);
    k_out<<<(N_VAR + 127) / 128, 128>>>(node_rel_w, node_rel_b, node_root_w, var_feats, out_node, 0);
    k_out<<<(N_CSTR + 127) / 128, 128>>>(cstr_rel_w, cstr_rel_b, cstr_root_w, cstr_feats, out_cstr, 1);
}